// round 4
// baseline (speedup 1.0000x reference)
#include <cuda_runtime.h>
#include <math.h>
#include <stdint.h>

#define NN   50000
#define DD   96
#define EE   800000
#define GG   2048
#define LL   64
#define HH   8
#define D2   192
#define EPSV 0.3f
#define QSCALE 0.2886751345948129f  // 1/sqrt(12)
#define RW   24                      // float4 per row (96/4)

// ---------------- device scratch (no allocations allowed) ----------------
__device__ int    g_deg[NN];
__device__ int    g_offs[NN + 1];
__device__ int    g_cur[NN];
__device__ __align__(16) int    g_col[EE];
__device__ __align__(16) int    g_erow[EE];
__device__ __align__(16) float2 g_ecc[EE];    // (col as float bits, coef)
__device__ float  g_dinv[NN];
__device__ float2 g_glr1[NN];
__device__ float2 g_glr2[NN];
__device__ __align__(16) float  g_Y[NN*DD];
__device__ __align__(16) float  g_S[NN*DD];
__device__ __align__(16) float  g_A[NN*DD];
__device__ __align__(16) float  g_B[NN*DD];
__device__ __align__(16) float  g_CAT[NN*D2];
__device__ __align__(16) float  g_H[NN*DD];
__device__ __align__(16) float  g_KN[NN*DD];
__device__ __align__(16) float  g_VN[NN*DD];
__device__ float  g_WtLin[D2*DD];
__device__ float  g_WtKV[DD*D2];
__device__ float  g_WtQ[DD*DD];
__device__ float  g_WtO[DD*DD];

// ---------------- small helpers ----------------
__device__ __forceinline__ float warp_sum(float v) {
    #pragma unroll
    for (int o = 16; o > 0; o >>= 1) v += __shfl_xor_sync(0xffffffffu, v, o);
    return v;
}

// ---------------- CSR construction ----------------
__global__ void k_zero_deg() {
    int i = blockIdx.x * blockDim.x + threadIdx.x;
    if (i < NN) g_deg[i] = 0;
}

__global__ void k_count(const int* __restrict__ edges) {
    int e = blockIdx.x * blockDim.x + threadIdx.x;
    if (e < EE) atomicAdd(&g_deg[edges[e]], 1);
}

__global__ void k_scan() {
    __shared__ int sh[1024];
    const int CH = (NN + 1023) / 1024;
    int tid = threadIdx.x;
    int begin = tid * CH;
    int end = min(begin + CH, NN);
    int sum = 0;
    for (int i = begin; i < end; i++) sum += g_deg[i];
    sh[tid] = sum;
    __syncthreads();
    for (int off = 1; off < 1024; off <<= 1) {
        int v = (tid >= off) ? sh[tid - off] : 0;
        __syncthreads();
        sh[tid] += v;
        __syncthreads();
    }
    int run = sh[tid] - sum;
    for (int i = begin; i < end; i++) {
        g_offs[i] = run;
        g_cur[i]  = run;
        int d = g_deg[i];
        g_dinv[i] = (d > 0) ? rsqrtf((float)d) : 0.f;
        run += d;
    }
    if (tid == 1023) g_offs[NN] = run;
}

__global__ void k_fill(const int* __restrict__ edges) {
    int e = blockIdx.x * blockDim.x + threadIdx.x;
    if (e >= EE) return;
    int row = edges[e];
    int col = edges[EE + e];
    int pos = atomicAdd(&g_cur[row], 1);
    g_col[pos]  = col;
    g_erow[pos] = row;
}

// ---------------- edge-parallel coef: (col, coef) packed ----------------
__global__ void k_coef(const float2* __restrict__ glr) {
    int e = blockIdx.x * blockDim.x + threadIdx.x;
    if (e >= EE) return;
    int row = g_erow[e];
    int col = g_col[e];
    float coef = tanhf(glr[row].x + glr[col].y) * g_dinv[row] * g_dinv[col];
    g_ecc[e] = make_float2(__int_as_float(col), coef);
}

// ---------------- gl/gr for layer-1 input (x), computed once ----------------
__global__ void k_glr1(const float* __restrict__ x,
                       const float* __restrict__ al,
                       const float* __restrict__ ar) {
    int n = (blockIdx.x * blockDim.x + threadIdx.x) >> 5;
    int lane = threadIdx.x & 31;
    if (n >= NN) return;
    int base = n * DD;
    float gl = 0.f, gr = 0.f;
    #pragma unroll
    for (int i = 0; i < 3; i++) {
        int d = lane + 32 * i;
        float y = x[base + d];
        gl += y * al[d];
        gr += y * ar[d];
    }
    gl = warp_sum(gl);
    gr = warp_sum(gr);
    if (lane == 0) g_glr1[n] = make_float2(gl, gr);
}

// ---------------- gather core ----------------
// acc = EPS*x[n] + sum_j coef_j * src[col_j]; lane<24 handles one float4.
__device__ __forceinline__ float4 gather_row(const float4* __restrict__ src4,
                                             const float4* __restrict__ x4,
                                             int n, int lane, bool act) {
    float4 acc = make_float4(0.f, 0.f, 0.f, 0.f);
    if (act) {
        float4 xv = x4[n * RW + lane];
        acc = make_float4(EPSV * xv.x, EPSV * xv.y, EPSV * xv.z, EPSV * xv.w);
    }
    int s = g_offs[n], e = g_offs[n + 1];
    int j = s;
    for (; j + 4 <= e; j += 4) {
        float2 c0 = g_ecc[j + 0];
        float2 c1 = g_ecc[j + 1];
        float2 c2 = g_ecc[j + 2];
        float2 c3 = g_ecc[j + 3];
        if (act) {
            float4 v0 = src4[__float_as_int(c0.x) * RW + lane];
            float4 v1 = src4[__float_as_int(c1.x) * RW + lane];
            float4 v2 = src4[__float_as_int(c2.x) * RW + lane];
            float4 v3 = src4[__float_as_int(c3.x) * RW + lane];
            acc.x = fmaf(c0.y, v0.x, acc.x); acc.y = fmaf(c0.y, v0.y, acc.y);
            acc.z = fmaf(c0.y, v0.z, acc.z); acc.w = fmaf(c0.y, v0.w, acc.w);
            acc.x = fmaf(c1.y, v1.x, acc.x); acc.y = fmaf(c1.y, v1.y, acc.y);
            acc.z = fmaf(c1.y, v1.z, acc.z); acc.w = fmaf(c1.y, v1.w, acc.w);
            acc.x = fmaf(c2.y, v2.x, acc.x); acc.y = fmaf(c2.y, v2.y, acc.y);
            acc.z = fmaf(c2.y, v2.z, acc.z); acc.w = fmaf(c2.y, v2.w, acc.w);
            acc.x = fmaf(c3.y, v3.x, acc.x); acc.y = fmaf(c3.y, v3.y, acc.y);
            acc.z = fmaf(c3.y, v3.z, acc.z); acc.w = fmaf(c3.y, v3.w, acc.w);
        }
    }
    for (; j < e; j++) {
        float2 c = g_ecc[j];
        if (act) {
            float4 v = src4[__float_as_int(c.x) * RW + lane];
            acc.x = fmaf(c.y, v.x, acc.x); acc.y = fmaf(c.y, v.y, acc.y);
            acc.z = fmaf(c.y, v.z, acc.z); acc.w = fmaf(c.y, v.w, acc.w);
        }
    }
    return acc;
}

// layer-1: src=x, dst=Y (relu), epilogue computes glr2
__global__ void k_gatherA(const float4* __restrict__ x4,
                          const float4* __restrict__ al2,
                          const float4* __restrict__ ar2,
                          float4* __restrict__ y4) {
    int n = (blockIdx.x * blockDim.x + threadIdx.x) >> 5;
    int lane = threadIdx.x & 31;
    if (n >= NN) return;
    bool act = lane < RW;
    float4 acc = gather_row(x4, x4, n, lane, act);
    float gl = 0.f, gr = 0.f;
    if (act) {
        acc.x = fmaxf(acc.x, 0.f); acc.y = fmaxf(acc.y, 0.f);
        acc.z = fmaxf(acc.z, 0.f); acc.w = fmaxf(acc.w, 0.f);
        y4[n * RW + lane] = acc;
        float4 a = al2[lane];
        float4 r = ar2[lane];
        gl = acc.x * a.x + acc.y * a.y + acc.z * a.z + acc.w * a.w;
        gr = acc.x * r.x + acc.y * r.y + acc.z * r.z + acc.w * r.w;
    }
    gl = warp_sum(gl);
    gr = warp_sum(gr);
    if (lane == 0) g_glr2[n] = make_float2(gl, gr);
}

// layer-2: src=Y, dst=outbuf (no relu)
__global__ void k_gatherB(const float4* __restrict__ y4,
                          const float4* __restrict__ x4,
                          float4* __restrict__ out4) {
    int n = (blockIdx.x * blockDim.x + threadIdx.x) >> 5;
    int lane = threadIdx.x & 31;
    if (n >= NN) return;
    bool act = lane < RW;
    float4 acc = gather_row(y4, x4, n, lane, act);
    if (act) out4[n * RW + lane] = acc;
}

// ---------------- gating + concat ----------------
__global__ void k_combine(const float* __restrict__ x,
                          const float* __restrict__ wga,
                          const float* __restrict__ bga,
                          const float* __restrict__ wgb,
                          const float* __restrict__ bgb) {
    int n = (blockIdx.x * blockDim.x + threadIdx.x) >> 5;
    int lane = threadIdx.x & 31;
    if (n >= NN) return;
    int base = n * DD;
    float l0 = 0.f, l1 = 0.f, m0 = 0.f, m1 = 0.f;
    float sv[3], av[3], bv[3];
    #pragma unroll
    for (int i = 0; i < 3; i++) {
        int d = lane + 32 * i;
        float xx = x[base + d];
        l0 += xx * wga[d];
        l1 += xx * wga[DD + d];
        m0 += xx * wgb[d];
        m1 += xx * wgb[DD + d];
        sv[i] = fmaxf(g_S[base + d], 0.f);
        av[i] = fmaxf(g_A[base + d], 0.f);
        bv[i] = fmaxf(g_B[base + d], 0.f);
    }
    l0 = warp_sum(l0); l1 = warp_sum(l1);
    m0 = warp_sum(m0); m1 = warp_sum(m1);
    l0 += bga[0]; l1 += bga[1];
    m0 += bgb[0]; m1 += bgb[1];
    float ga0 = 1.f / (1.f + __expf(l1 - l0));
    float ga1 = 1.f - ga0;
    float gb0 = 1.f / (1.f + __expf(m1 - m0));
    float gb1 = 1.f - gb0;
    #pragma unroll
    for (int i = 0; i < 3; i++) {
        int d = lane + 32 * i;
        g_CAT[n * D2 + d]      = ga0 * av[i] + ga1 * sv[i];
        g_CAT[n * D2 + DD + d] = gb0 * bv[i] + gb1 * sv[i];
    }
}

__global__ void k_transpose(const float* __restrict__ w_lin,
                            const float* __restrict__ w_qkv,
                            const float* __restrict__ w_o) {
    int t = blockIdx.x * blockDim.x + threadIdx.x;
    if (t >= D2 * DD) return;
    {
        int k = t / DD, j = t % DD;
        g_WtLin[t] = w_lin[j * D2 + k];
    }
    {
        int c = t / D2, r = t % D2;
        g_WtKV[t] = w_qkv[(DD + r) * DD + c];
    }
    if (t < DD * DD) {
        int c = t / DD, j = t % DD;
        g_WtQ[t] = w_qkv[j * DD + c];
        g_WtO[t] = w_o[j * DD + c];
    }
}

// h = relu(CAT @ w_lin^T + b_lin)
__global__ void k_gemm_h(const float* __restrict__ b_lin) {
    __shared__ float As[32 * D2];
    int j = threadIdx.x;
    int base = blockIdx.x * 32;
    int cnt = min(32, NN - base);
    for (int idx = j; idx < cnt * D2; idx += DD) {
        int r = idx / D2, c = idx % D2;
        As[r * D2 + c] = g_CAT[(base + r) * D2 + c];
    }
    __syncthreads();
    float acc[32];
    #pragma unroll
    for (int m = 0; m < 32; m++) acc[m] = 0.f;
    const float4* As4 = reinterpret_cast<const float4*>(As);
    #pragma unroll 4
    for (int k4 = 0; k4 < D2 / 4; k4++) {
        int k = k4 * 4;
        float w0 = g_WtLin[(k + 0) * DD + j];
        float w1 = g_WtLin[(k + 1) * DD + j];
        float w2 = g_WtLin[(k + 2) * DD + j];
        float w3 = g_WtLin[(k + 3) * DD + j];
        #pragma unroll
        for (int m = 0; m < 32; m++) {
            float4 a = As4[m * (D2 / 4) + k4];
            acc[m] += a.x * w0 + a.y * w1 + a.z * w2 + a.w * w3;
        }
    }
    float bj = b_lin[j];
    for (int m = 0; m < cnt; m++)
        g_H[(base + m) * DD + j] = fmaxf(acc[m] + bj, 0.f);
}

// K,V per node
__global__ void k_gemm_kv(const float* __restrict__ b_qkv) {
    __shared__ float As[32 * DD];
    int j = threadIdx.x;
    int base = blockIdx.x * 32;
    int cnt = min(32, NN - base);
    for (int idx = j; idx < cnt * DD; idx += D2) {
        int r = idx / DD, c = idx % DD;
        As[r * DD + c] = g_H[(base + r) * DD + c];
    }
    __syncthreads();
    float acc[32];
    #pragma unroll
    for (int m = 0; m < 32; m++) acc[m] = 0.f;
    const float4* As4 = reinterpret_cast<const float4*>(As);
    #pragma unroll 4
    for (int k4 = 0; k4 < DD / 4; k4++) {
        int k = k4 * 4;
        float w0 = g_WtKV[(k + 0) * D2 + j];
        float w1 = g_WtKV[(k + 1) * D2 + j];
        float w2 = g_WtKV[(k + 2) * D2 + j];
        float w3 = g_WtKV[(k + 3) * D2 + j];
        #pragma unroll
        for (int m = 0; m < 32; m++) {
            float4 a = As4[m * (DD / 4) + k4];
            acc[m] += a.x * w0 + a.y * w1 + a.z * w2 + a.w * w3;
        }
    }
    float bj = b_qkv[DD + j];
    if (j < DD) {
        for (int m = 0; m < cnt; m++)
            g_KN[(base + m) * DD + j] = acc[m] + bj;
    } else {
        int jj = j - DD;
        for (int m = 0; m < cnt; m++)
            g_VN[(base + m) * DD + jj] = acc[m] + bj;
    }
}

// attention: block per group (128 threads); only row l=0 needed.
__global__ void k_attn(const int* __restrict__ target_ids,
                       const int* __restrict__ target_lens,
                       const float* __restrict__ b_qkv,
                       const float* __restrict__ b_o,
                       float* __restrict__ out) {
    __shared__ int   sn[LL];
    __shared__ int   slen;
    __shared__ float hrow[DD];
    __shared__ float qs[DD];
    __shared__ float Ks[LL * 97];
    __shared__ float sc[HH * 68];
    __shared__ float cs[DD];

    int g = blockIdx.x;
    int tid = threadIdx.x;

    if (tid < LL) sn[tid] = target_ids[g * LL + tid];
    if (tid == 64) slen = target_lens[g];
    __syncthreads();

    if (tid < DD) hrow[tid] = g_H[sn[0] * DD + tid];
    __syncthreads();

    for (int idx = tid; idx < LL * DD; idx += blockDim.x) {
        int m = idx / DD, c = idx % DD;
        Ks[m * 97 + c] = g_KN[sn[m] * DD + c];
    }
    if (tid < DD) {
        float s = 0.f;
        #pragma unroll 8
        for (int c = 0; c < DD; c++) s += hrow[c] * g_WtQ[c * DD + tid];
        qs[tid] = (s + b_qkv[tid]) * QSCALE;
    }
    __syncthreads();

    int len = slen;
    if (tid < LL && tid < len) {
        int m = tid;
        const float* kr = &Ks[m * 97];
        #pragma unroll
        for (int h = 0; h < HH; h++) {
            float s = 0.f;
            #pragma unroll
            for (int d = 0; d < 12; d++) s += qs[h * 12 + d] * kr[h * 12 + d];
            sc[h * 68 + m] = s;
        }
    }
    __syncthreads();

    if (tid < HH) {
        float* row = &sc[tid * 68];
        float mx = row[0];
        for (int m = 1; m < len; m++) mx = fmaxf(mx, row[m]);
        float sum = 0.f;
        for (int m = 0; m < len; m++) {
            float e = __expf(row[m] - mx);
            row[m] = e;
            sum += e;
        }
        float inv = 1.f / sum;
        for (int m = 0; m < len; m++) row[m] *= inv;
    }
    __syncthreads();

    if (tid < LL) {
        float wv = 0.f;
        if (tid < len) {
            #pragma unroll
            for (int h = 0; h < HH; h++) wv += sc[h * 68 + tid];
            wv *= (1.f / HH);
        }
        out[GG * DD + g * LL + tid] = wv;
    }
    if (tid < DD) {
        int h = tid / 12;
        float a = 0.f;
        for (int m = 0; m < len; m++)
            a += sc[h * 68 + m] * g_VN[sn[m] * DD + tid];
        cs[tid] = a;
    }
    __syncthreads();

    if (tid < DD) {
        float o = b_o[tid];
        #pragma unroll 8
        for (int c = 0; c < DD; c++) o += cs[c] * g_WtO[c * DD + tid];
        out[g * DD + tid] = o;
    }
}

// ---------------- launch ----------------
extern "C" void kernel_launch(void* const* d_in, const int* in_sizes, int n_in,
                              void* d_out, int out_size) {
    const float* x     = (const float*)d_in[0];
    const float* a_l   = (const float*)d_in[1];
    const float* a_r   = (const float*)d_in[2];
    const float* w_ga  = (const float*)d_in[3];
    const float* b_ga  = (const float*)d_in[4];
    const float* w_gb  = (const float*)d_in[5];
    const float* b_gb  = (const float*)d_in[6];
    const float* w_lin = (const float*)d_in[7];
    const float* b_lin = (const float*)d_in[8];
    const float* w_qkv = (const float*)d_in[9];
    const float* b_qkv = (const float*)d_in[10];
    const float* w_o   = (const float*)d_in[11];
    const float* b_o   = (const float*)d_in[12];
    const int*   grph[3] = {(const int*)d_in[13], (const int*)d_in[14], (const int*)d_in[15]};
    const int*   target_ids  = (const int*)d_in[16];
    const int*   target_lens = (const int*)d_in[17];
    float* out = (float*)d_out;

    float *pS, *pA, *pB, *pY;
    float2 *pG1, *pG2;
    cudaGetSymbolAddress((void**)&pS,  g_S);
    cudaGetSymbolAddress((void**)&pA,  g_A);
    cudaGetSymbolAddress((void**)&pB,  g_B);
    cudaGetSymbolAddress((void**)&pY,  g_Y);
    cudaGetSymbolAddress((void**)&pG1, g_glr1);
    cudaGetSymbolAddress((void**)&pG2, g_glr2);
    float* outs[3] = {pS, pA, pB};

    const float4* x4  = (const float4*)x;
    float4* y4        = (float4*)pY;
    const float4* al2 = (const float4*)(a_l + DD);
    const float4* ar2 = (const float4*)(a_r + DD);

    const int nodeBlocks = (NN + 7) / 8;    // warp per node, 256 thr
    const int edgeThr    = (EE + 255) / 256;

    k_transpose<<<(D2 * DD + 255) / 256, 256>>>(w_lin, w_qkv, w_o);
    k_glr1<<<nodeBlocks, 256>>>(x, a_l, a_r);

    for (int i = 0; i < 3; i++) {
        k_zero_deg<<<(NN + 255) / 256, 256>>>();
        k_count<<<edgeThr, 256>>>(grph[i]);
        k_scan<<<1, 1024>>>();
        k_fill<<<edgeThr, 256>>>(grph[i]);
        k_coef<<<edgeThr, 256>>>(pG1);
        k_gatherA<<<nodeBlocks, 256>>>(x4, al2, ar2, y4);
        k_coef<<<edgeThr, 256>>>(pG2);
        k_gatherB<<<nodeBlocks, 256>>>((const float4*)pY, x4, (float4*)outs[i]);
    }

    k_combine<<<nodeBlocks, 256>>>(x, w_ga, b_ga, w_gb, b_gb);
    k_gemm_h<<<(NN + 31) / 32, DD>>>(b_lin);
    k_gemm_kv<<<(NN + 31) / 32, D2>>>(b_qkv);
    k_attn<<<GG, 128>>>(target_ids, target_lens, b_qkv, b_o, out);
}

// round 5
// speedup vs baseline: 1.4716x; 1.4716x over previous
#include <cuda_runtime.h>
#include <math.h>
#include <stdint.h>

#define NN   50000
#define NN1  50001
#define DD   96
#define EE   800000
#define GG   2048
#define LL   64
#define HH   8
#define D2   192
#define EPSV 0.3f
#define QSCALE 0.2886751345948129f  // 1/sqrt(12)
#define RW   24                      // float4 per row (96/4)
#define SBLK 196                     // scan blocks per graph (196*256 >= 50000)
#define EBLK 3125                    // edge blocks per graph (3125*256 = 800000)
#define NODEB 6250                   // node blocks (warp/node, 256 thr)

// ---------------- device scratch (no allocations allowed) ----------------
__device__ int    g_deg[3*NN];
__device__ int    g_offs[3*NN1];
__device__ int    g_cur[3*NN];
__device__ int    g_bsum[3*SBLK];
__device__ int    g_bscan[3*SBLK];
__device__ __align__(16) int    g_col[3*EE];
__device__ __align__(16) int    g_erow[3*EE];
__device__ __align__(16) float2 g_ecc[3*EE];    // (col as int bits, coef)
__device__ float  g_dinv[3*NN];
__device__ float2 g_glr1[NN];
__device__ float2 g_glr2[3*NN];
__device__ __align__(16) float  g_Y[3*NN*DD];
__device__ __align__(16) float  g_SAB[3*NN*DD];  // [S | A | B]
__device__ __align__(16) float  g_CAT[NN*D2];
__device__ __align__(16) float  g_H[NN*DD];
__device__ __align__(16) float  g_KN[NN*DD];
__device__ __align__(16) float  g_VN[NN*DD];
__device__ float  g_WtLin[D2*DD];
__device__ float  g_WtKV[DD*D2];
__device__ float  g_WtQ[DD*DD];
__device__ float  g_WtO[DD*DD];

// ---------------- small helpers ----------------
__device__ __forceinline__ float warp_sum(float v) {
    #pragma unroll
    for (int o = 16; o > 0; o >>= 1) v += __shfl_xor_sync(0xffffffffu, v, o);
    return v;
}

// ---------------- CSR construction (batched over 3 graphs) ----------------
__global__ void k_zero3() {
    int i = blockIdx.x * blockDim.x + threadIdx.x;
    if (i < 3 * NN) g_deg[i] = 0;
}

__global__ void k_count3(const int* __restrict__ e0,
                         const int* __restrict__ e1,
                         const int* __restrict__ e2) {
    int g = blockIdx.y;
    const int* ep = (g == 0) ? e0 : (g == 1) ? e1 : e2;
    int e = blockIdx.x * blockDim.x + threadIdx.x;
    if (e < EE) atomicAdd(&g_deg[g * NN + ep[e]], 1);
}

// phase A: per-block sums + dinv (coalesced)
__global__ void k_scanA() {
    __shared__ int sh[256];
    int g = blockIdx.y;
    int i = blockIdx.x * 256 + threadIdx.x;
    int d = (i < NN) ? g_deg[g * NN + i] : 0;
    if (i < NN) g_dinv[g * NN + i] = (d > 0) ? rsqrtf((float)d) : 0.f;
    sh[threadIdx.x] = d;
    __syncthreads();
    #pragma unroll
    for (int o = 128; o > 0; o >>= 1) {
        if (threadIdx.x < o) sh[threadIdx.x] += sh[threadIdx.x + o];
        __syncthreads();
    }
    if (threadIdx.x == 0) g_bsum[g * SBLK + blockIdx.x] = sh[0];
}

// phase B: scan 196 partials per graph (1 block)
__global__ void k_scanB() {
    __shared__ int sh[256];
    int tid = threadIdx.x;
    for (int g = 0; g < 3; g++) {
        int v = (tid < SBLK) ? g_bsum[g * SBLK + tid] : 0;
        sh[tid] = v;
        __syncthreads();
        #pragma unroll
        for (int o = 1; o < 256; o <<= 1) {
            int t = (tid >= o) ? sh[tid - o] : 0;
            __syncthreads();
            sh[tid] += t;
            __syncthreads();
        }
        if (tid < SBLK) g_bscan[g * SBLK + tid] = sh[tid] - v;  // exclusive
        if (tid == 255) g_offs[g * NN1 + NN] = sh[255];         // total
        __syncthreads();
    }
}

// phase C: per-block exclusive scan + offset -> offs, cur (coalesced)
__global__ void k_scanC() {
    __shared__ int sh[256];
    int g = blockIdx.y;
    int i = blockIdx.x * 256 + threadIdx.x;
    int tid = threadIdx.x;
    int d = (i < NN) ? g_deg[g * NN + i] : 0;
    sh[tid] = d;
    __syncthreads();
    #pragma unroll
    for (int o = 1; o < 256; o <<= 1) {
        int t = (tid >= o) ? sh[tid - o] : 0;
        __syncthreads();
        sh[tid] += t;
        __syncthreads();
    }
    if (i < NN) {
        int off = g_bscan[g * SBLK + blockIdx.x] + sh[tid] - d;  // exclusive
        g_offs[g * NN1 + i] = off;
        g_cur[g * NN + i]   = off;
    }
}

// fill CSR + coef for layer 1 (glr1 is graph-independent)
__global__ void k_fill3(const int* __restrict__ e0,
                        const int* __restrict__ e1,
                        const int* __restrict__ e2) {
    int g = blockIdx.y;
    const int* ep = (g == 0) ? e0 : (g == 1) ? e1 : e2;
    int e = blockIdx.x * blockDim.x + threadIdx.x;
    if (e >= EE) return;
    int row = ep[e];
    int col = ep[EE + e];
    int pos = atomicAdd(&g_cur[g * NN + row], 1);
    g_col[g * EE + pos]  = col;
    g_erow[g * EE + pos] = row;
    float coef = tanhf(g_glr1[row].x + g_glr1[col].y)
               * g_dinv[g * NN + row] * g_dinv[g * NN + col];
    g_ecc[g * EE + pos] = make_float2(__int_as_float(col), coef);
}

// coef for layer 2 (needs per-graph glr2)
__global__ void k_coef2_3() {
    int g = blockIdx.y;
    int e = blockIdx.x * blockDim.x + threadIdx.x;
    if (e >= EE) return;
    int row = g_erow[g * EE + e];
    int col = g_col[g * EE + e];
    float coef = tanhf(g_glr2[g * NN + row].x + g_glr2[g * NN + col].y)
               * g_dinv[g * NN + row] * g_dinv[g * NN + col];
    g_ecc[g * EE + e] = make_float2(__int_as_float(col), coef);
}

// ---------------- gl/gr for layer-1 input (x), computed once ----------------
__global__ void k_glr1(const float* __restrict__ x,
                       const float* __restrict__ al,
                       const float* __restrict__ ar) {
    int n = (blockIdx.x * blockDim.x + threadIdx.x) >> 5;
    int lane = threadIdx.x & 31;
    if (n >= NN) return;
    int base = n * DD;
    float gl = 0.f, gr = 0.f;
    #pragma unroll
    for (int i = 0; i < 3; i++) {
        int d = lane + 32 * i;
        float y = x[base + d];
        gl += y * al[d];
        gr += y * ar[d];
    }
    gl = warp_sum(gl);
    gr = warp_sum(gr);
    if (lane == 0) g_glr1[n] = make_float2(gl, gr);
}

// ---------------- gather core: acc = EPS*x[n] + sum coef_j * src[col_j] ----
__device__ __forceinline__ float4 gather_row(const float4* __restrict__ src4,
                                             const float4* __restrict__ x4,
                                             const float2* __restrict__ ecc,
                                             int s, int e,
                                             int n, int lane, bool act) {
    float4 acc = make_float4(0.f, 0.f, 0.f, 0.f);
    if (act) {
        float4 xv = __ldg(&x4[n * RW + lane]);
        acc = make_float4(EPSV * xv.x, EPSV * xv.y, EPSV * xv.z, EPSV * xv.w);
    }
    int j = s;
    for (; j + 8 <= e; j += 8) {
        float2 c0 = __ldg(&ecc[j + 0]);
        float2 c1 = __ldg(&ecc[j + 1]);
        float2 c2 = __ldg(&ecc[j + 2]);
        float2 c3 = __ldg(&ecc[j + 3]);
        float2 c4 = __ldg(&ecc[j + 4]);
        float2 c5 = __ldg(&ecc[j + 5]);
        float2 c6 = __ldg(&ecc[j + 6]);
        float2 c7 = __ldg(&ecc[j + 7]);
        if (act) {
            float4 v0 = __ldg(&src4[__float_as_int(c0.x) * RW + lane]);
            float4 v1 = __ldg(&src4[__float_as_int(c1.x) * RW + lane]);
            float4 v2 = __ldg(&src4[__float_as_int(c2.x) * RW + lane]);
            float4 v3 = __ldg(&src4[__float_as_int(c3.x) * RW + lane]);
            float4 v4 = __ldg(&src4[__float_as_int(c4.x) * RW + lane]);
            float4 v5 = __ldg(&src4[__float_as_int(c5.x) * RW + lane]);
            float4 v6 = __ldg(&src4[__float_as_int(c6.x) * RW + lane]);
            float4 v7 = __ldg(&src4[__float_as_int(c7.x) * RW + lane]);
            acc.x = fmaf(c0.y, v0.x, acc.x); acc.y = fmaf(c0.y, v0.y, acc.y);
            acc.z = fmaf(c0.y, v0.z, acc.z); acc.w = fmaf(c0.y, v0.w, acc.w);
            acc.x = fmaf(c1.y, v1.x, acc.x); acc.y = fmaf(c1.y, v1.y, acc.y);
            acc.z = fmaf(c1.y, v1.z, acc.z); acc.w = fmaf(c1.y, v1.w, acc.w);
            acc.x = fmaf(c2.y, v2.x, acc.x); acc.y = fmaf(c2.y, v2.y, acc.y);
            acc.z = fmaf(c2.y, v2.z, acc.z); acc.w = fmaf(c2.y, v2.w, acc.w);
            acc.x = fmaf(c3.y, v3.x, acc.x); acc.y = fmaf(c3.y, v3.y, acc.y);
            acc.z = fmaf(c3.y, v3.z, acc.z); acc.w = fmaf(c3.y, v3.w, acc.w);
            acc.x = fmaf(c4.y, v4.x, acc.x); acc.y = fmaf(c4.y, v4.y, acc.y);
            acc.z = fmaf(c4.y, v4.z, acc.z); acc.w = fmaf(c4.y, v4.w, acc.w);
            acc.x = fmaf(c5.y, v5.x, acc.x); acc.y = fmaf(c5.y, v5.y, acc.y);
            acc.z = fmaf(c5.y, v5.z, acc.z); acc.w = fmaf(c5.y, v5.w, acc.w);
            acc.x = fmaf(c6.y, v6.x, acc.x); acc.y = fmaf(c6.y, v6.y, acc.y);
            acc.z = fmaf(c6.y, v6.z, acc.z); acc.w = fmaf(c6.y, v6.w, acc.w);
            acc.x = fmaf(c7.y, v7.x, acc.x); acc.y = fmaf(c7.y, v7.y, acc.y);
            acc.z = fmaf(c7.y, v7.z, acc.z); acc.w = fmaf(c7.y, v7.w, acc.w);
        }
    }
    for (; j < e; j++) {
        float2 c = __ldg(&ecc[j]);
        if (act) {
            float4 v = __ldg(&src4[__float_as_int(c.x) * RW + lane]);
            acc.x = fmaf(c.y, v.x, acc.x); acc.y = fmaf(c.y, v.y, acc.y);
            acc.z = fmaf(c.y, v.z, acc.z); acc.w = fmaf(c.y, v.w, acc.w);
        }
    }
    return acc;
}

// layer-1 gather (all 3 graphs): src=x, dst=Y[g] (relu), epilogue glr2[g]
__global__ void k_gatherA3(const float4* __restrict__ x4,
                           const float4* __restrict__ al2,
                           const float4* __restrict__ ar2) {
    int g = blockIdx.y;
    int n = (blockIdx.x * blockDim.x + threadIdx.x) >> 5;
    int lane = threadIdx.x & 31;
    if (n >= NN) return;
    bool act = lane < RW;
    int s = g_offs[g * NN1 + n], e = g_offs[g * NN1 + n + 1];
    float4 acc = gather_row(x4, x4, g_ecc + g * EE, s, e, n, lane, act);
    float gl = 0.f, gr = 0.f;
    if (act) {
        acc.x = fmaxf(acc.x, 0.f); acc.y = fmaxf(acc.y, 0.f);
        acc.z = fmaxf(acc.z, 0.f); acc.w = fmaxf(acc.w, 0.f);
        reinterpret_cast<float4*>(g_Y)[(g * NN + n) * RW + lane] = acc;
        float4 a = __ldg(&al2[lane]);
        float4 r = __ldg(&ar2[lane]);
        gl = acc.x * a.x + acc.y * a.y + acc.z * a.z + acc.w * a.w;
        gr = acc.x * r.x + acc.y * r.y + acc.z * r.z + acc.w * r.w;
    }
    gl = warp_sum(gl);
    gr = warp_sum(gr);
    if (lane == 0) g_glr2[g * NN + n] = make_float2(gl, gr);
}

// layer-2 gather (all 3 graphs): src=Y[g], dst=SAB[g]
__global__ void k_gatherB3(const float4* __restrict__ x4) {
    int g = blockIdx.y;
    int n = (blockIdx.x * blockDim.x + threadIdx.x) >> 5;
    int lane = threadIdx.x & 31;
    if (n >= NN) return;
    bool act = lane < RW;
    int s = g_offs[g * NN1 + n], e = g_offs[g * NN1 + n + 1];
    const float4* src4 = reinterpret_cast<const float4*>(g_Y) + g * NN * RW;
    float4 acc = gather_row(src4, x4, g_ecc + g * EE, s, e, n, lane, act);
    if (act)
        reinterpret_cast<float4*>(g_SAB)[(g * NN + n) * RW + lane] = acc;
}

// ---------------- gating + concat ----------------
__global__ void k_combine(const float* __restrict__ x,
                          const float* __restrict__ wga,
                          const float* __restrict__ bga,
                          const float* __restrict__ wgb,
                          const float* __restrict__ bgb) {
    int n = (blockIdx.x * blockDim.x + threadIdx.x) >> 5;
    int lane = threadIdx.x & 31;
    if (n >= NN) return;
    int base = n * DD;
    float l0 = 0.f, l1 = 0.f, m0 = 0.f, m1 = 0.f;
    float sv[3], av[3], bv[3];
    #pragma unroll
    for (int i = 0; i < 3; i++) {
        int d = lane + 32 * i;
        float xx = x[base + d];
        l0 += xx * wga[d];
        l1 += xx * wga[DD + d];
        m0 += xx * wgb[d];
        m1 += xx * wgb[DD + d];
        sv[i] = fmaxf(g_SAB[0 * NN * DD + base + d], 0.f);
        av[i] = fmaxf(g_SAB[1 * NN * DD + base + d], 0.f);
        bv[i] = fmaxf(g_SAB[2 * NN * DD + base + d], 0.f);
    }
    l0 = warp_sum(l0); l1 = warp_sum(l1);
    m0 = warp_sum(m0); m1 = warp_sum(m1);
    l0 += bga[0]; l1 += bga[1];
    m0 += bgb[0]; m1 += bgb[1];
    float ga0 = 1.f / (1.f + __expf(l1 - l0));
    float ga1 = 1.f - ga0;
    float gb0 = 1.f / (1.f + __expf(m1 - m0));
    float gb1 = 1.f - gb0;
    #pragma unroll
    for (int i = 0; i < 3; i++) {
        int d = lane + 32 * i;
        g_CAT[n * D2 + d]      = ga0 * av[i] + ga1 * sv[i];
        g_CAT[n * D2 + DD + d] = gb0 * bv[i] + gb1 * sv[i];
    }
}

__global__ void k_transpose(const float* __restrict__ w_lin,
                            const float* __restrict__ w_qkv,
                            const float* __restrict__ w_o) {
    int t = blockIdx.x * blockDim.x + threadIdx.x;
    if (t >= D2 * DD) return;
    {
        int k = t / DD, j = t % DD;
        g_WtLin[t] = w_lin[j * D2 + k];
    }
    {
        int c = t / D2, r = t % D2;
        g_WtKV[t] = w_qkv[(DD + r) * DD + c];
    }
    if (t < DD * DD) {
        int c = t / DD, j = t % DD;
        g_WtQ[t] = w_qkv[j * DD + c];
        g_WtO[t] = w_o[j * DD + c];
    }
}

// h = relu(CAT @ w_lin^T + b_lin)
__global__ void k_gemm_h(const float* __restrict__ b_lin) {
    __shared__ float As[32 * D2];
    int j = threadIdx.x;
    int base = blockIdx.x * 32;
    int cnt = min(32, NN - base);
    for (int idx = j; idx < cnt * D2; idx += DD) {
        int r = idx / D2, c = idx % D2;
        As[r * D2 + c] = g_CAT[(base + r) * D2 + c];
    }
    __syncthreads();
    float acc[32];
    #pragma unroll
    for (int m = 0; m < 32; m++) acc[m] = 0.f;
    const float4* As4 = reinterpret_cast<const float4*>(As);
    #pragma unroll 4
    for (int k4 = 0; k4 < D2 / 4; k4++) {
        int k = k4 * 4;
        float w0 = g_WtLin[(k + 0) * DD + j];
        float w1 = g_WtLin[(k + 1) * DD + j];
        float w2 = g_WtLin[(k + 2) * DD + j];
        float w3 = g_WtLin[(k + 3) * DD + j];
        #pragma unroll
        for (int m = 0; m < 32; m++) {
            float4 a = As4[m * (D2 / 4) + k4];
            acc[m] += a.x * w0 + a.y * w1 + a.z * w2 + a.w * w3;
        }
    }
    float bj = b_lin[j];
    for (int m = 0; m < cnt; m++)
        g_H[(base + m) * DD + j] = fmaxf(acc[m] + bj, 0.f);
}

// K,V per node
__global__ void k_gemm_kv(const float* __restrict__ b_qkv) {
    __shared__ float As[32 * DD];
    int j = threadIdx.x;
    int base = blockIdx.x * 32;
    int cnt = min(32, NN - base);
    for (int idx = j; idx < cnt * DD; idx += D2) {
        int r = idx / DD, c = idx % DD;
        As[r * DD + c] = g_H[(base + r) * DD + c];
    }
    __syncthreads();
    float acc[32];
    #pragma unroll
    for (int m = 0; m < 32; m++) acc[m] = 0.f;
    const float4* As4 = reinterpret_cast<const float4*>(As);
    #pragma unroll 4
    for (int k4 = 0; k4 < DD / 4; k4++) {
        int k = k4 * 4;
        float w0 = g_WtKV[(k + 0) * D2 + j];
        float w1 = g_WtKV[(k + 1) * D2 + j];
        float w2 = g_WtKV[(k + 2) * D2 + j];
        float w3 = g_WtKV[(k + 3) * D2 + j];
        #pragma unroll
        for (int m = 0; m < 32; m++) {
            float4 a = As4[m * (DD / 4) + k4];
            acc[m] += a.x * w0 + a.y * w1 + a.z * w2 + a.w * w3;
        }
    }
    float bj = b_qkv[DD + j];
    if (j < DD) {
        for (int m = 0; m < cnt; m++)
            g_KN[(base + m) * DD + j] = acc[m] + bj;
    } else {
        int jj = j - DD;
        for (int m = 0; m < cnt; m++)
            g_VN[(base + m) * DD + jj] = acc[m] + bj;
    }
}

// attention: block per group (128 threads); only row l=0 needed.
__global__ void k_attn(const int* __restrict__ target_ids,
                       const int* __restrict__ target_lens,
                       const float* __restrict__ b_qkv,
                       const float* __restrict__ b_o,
                       float* __restrict__ out) {
    __shared__ int   sn[LL];
    __shared__ int   slen;
    __shared__ float hrow[DD];
    __shared__ float qs[DD];
    __shared__ float Ks[LL * 97];
    __shared__ float sc[HH * 68];
    __shared__ float cs[DD];

    int g = blockIdx.x;
    int tid = threadIdx.x;

    if (tid < LL) sn[tid] = target_ids[g * LL + tid];
    if (tid == 64) slen = target_lens[g];
    __syncthreads();

    if (tid < DD) hrow[tid] = g_H[sn[0] * DD + tid];
    __syncthreads();

    for (int idx = tid; idx < LL * DD; idx += blockDim.x) {
        int m = idx / DD, c = idx % DD;
        Ks[m * 97 + c] = g_KN[sn[m] * DD + c];
    }
    if (tid < DD) {
        float s = 0.f;
        #pragma unroll 8
        for (int c = 0; c < DD; c++) s += hrow[c] * g_WtQ[c * DD + tid];
        qs[tid] = (s + b_qkv[tid]) * QSCALE;
    }
    __syncthreads();

    int len = slen;
    if (tid < LL && tid < len) {
        int m = tid;
        const float* kr = &Ks[m * 97];
        #pragma unroll
        for (int h = 0; h < HH; h++) {
            float s = 0.f;
            #pragma unroll
            for (int d = 0; d < 12; d++) s += qs[h * 12 + d] * kr[h * 12 + d];
            sc[h * 68 + m] = s;
        }
    }
    __syncthreads();

    if (tid < HH) {
        float* row = &sc[tid * 68];
        float mx = row[0];
        for (int m = 1; m < len; m++) mx = fmaxf(mx, row[m]);
        float sum = 0.f;
        for (int m = 0; m < len; m++) {
            float e = __expf(row[m] - mx);
            row[m] = e;
            sum += e;
        }
        float inv = 1.f / sum;
        for (int m = 0; m < len; m++) row[m] *= inv;
    }
    __syncthreads();

    if (tid < LL) {
        float wv = 0.f;
        if (tid < len) {
            #pragma unroll
            for (int h = 0; h < HH; h++) wv += sc[h * 68 + tid];
            wv *= (1.f / HH);
        }
        out[GG * DD + g * LL + tid] = wv;
    }
    if (tid < DD) {
        int h = tid / 12;
        float a = 0.f;
        for (int m = 0; m < len; m++)
            a += sc[h * 68 + m] * g_VN[sn[m] * DD + tid];
        cs[tid] = a;
    }
    __syncthreads();

    if (tid < DD) {
        float o = b_o[tid];
        #pragma unroll 8
        for (int c = 0; c < DD; c++) o += cs[c] * g_WtO[c * DD + tid];
        out[g * DD + tid] = o;
    }
}

// ---------------- launch ----------------
extern "C" void kernel_launch(void* const* d_in, const int* in_sizes, int n_in,
                              void* d_out, int out_size) {
    const float* x     = (const float*)d_in[0];
    const float* a_l   = (const float*)d_in[1];
    const float* a_r   = (const float*)d_in[2];
    const float* w_ga  = (const float*)d_in[3];
    const float* b_ga  = (const float*)d_in[4];
    const float* w_gb  = (const float*)d_in[5];
    const float* b_gb  = (const float*)d_in[6];
    const float* w_lin = (const float*)d_in[7];
    const float* b_lin = (const float*)d_in[8];
    const float* w_qkv = (const float*)d_in[9];
    const float* b_qkv = (const float*)d_in[10];
    const float* w_o   = (const float*)d_in[11];
    const float* b_o   = (const float*)d_in[12];
    const int*   e0    = (const int*)d_in[13];
    const int*   e1    = (const int*)d_in[14];
    const int*   e2    = (const int*)d_in[15];
    const int*   target_ids  = (const int*)d_in[16];
    const int*   target_lens = (const int*)d_in[17];
    float* out = (float*)d_out;

    const float4* x4  = (const float4*)x;
    const float4* al2 = (const float4*)(a_l + DD);
    const float4* ar2 = (const float4*)(a_r + DD);

    dim3 eg(EBLK, 3), sg(SBLK, 3), ng(NODEB, 3);

    k_transpose<<<(D2 * DD + 255) / 256, 256>>>(w_lin, w_qkv, w_o);
    k_glr1<<<NODEB, 256>>>(x, a_l, a_r);

    k_zero3<<<(3 * NN + 255) / 256, 256>>>();
    k_count3<<<eg, 256>>>(e0, e1, e2);
    k_scanA<<<sg, 256>>>();
    k_scanB<<<1, 256>>>();
    k_scanC<<<sg, 256>>>();
    k_fill3<<<eg, 256>>>(e0, e1, e2);
    k_gatherA3<<<ng, 256>>>(x4, al2, ar2);
    k_coef2_3<<<eg, 256>>>();
    k_gatherB3<<<ng, 256>>>(x4);

    k_combine<<<NODEB, 256>>>(x, w_ga, b_ga, w_gb, b_gb);
    k_gemm_h<<<(NN + 31) / 32, DD>>>(b_lin);
    k_gemm_kv<<<(NN + 31) / 32, D2>>>(b_qkv);
    k_attn<<<GG, 128>>>(target_ids, target_lens, b_qkv, b_o, out);
}

// round 7
// speedup vs baseline: 1.5984x; 1.0862x over previous
#include <cuda_runtime.h>
#include <cuda_fp16.h>
#include <math.h>
#include <stdint.h>

#define NN   50000
#define NN1  50001
#define DD   96
#define EE   800000
#define GG   2048
#define LL   64
#define HH   8
#define D2   192
#define EPSV 0.3f
#define QSCALE 0.2886751345948129f  // 1/sqrt(12)
#define RW   24                      // float4 per fp32 row (96/4); also 8B-chunks per fp16 row
#define SBLK 196
#define EBLK 3125
#define NODEB 6250

// ---------------- device scratch ----------------
__device__ int    g_deg[3*NN];
__device__ int    g_offs[3*NN1];
__device__ int    g_cur[3*NN];
__device__ int    g_bsum[3*SBLK];
__device__ int    g_bscan[3*SBLK];
__device__ __align__(16) int    g_erow[3*EE];
__device__ __align__(16) float2 g_ecc[3*EE];    // (col as int bits, coef)
__device__ float  g_dinv[3*NN];
__device__ float2 g_glr1[NN];
__device__ float2 g_glr2[3*NN];
__device__ __align__(16) __half g_X16[NN*DD];     // fp16 copy of x
__device__ __align__(16) __half g_Y16[3*NN*DD];   // fp16 relu(layer1 out)
__device__ __align__(16) float  g_SAB[3*NN*DD];   // [S | A | B] fp32
__device__ __align__(16) float  g_CAT[NN*D2];
__device__ __align__(16) float  g_H[NN*DD];
__device__ __align__(16) float  g_KN[NN*DD];
__device__ __align__(16) float  g_VN[NN*DD];
__device__ float  g_WtLin[D2*DD];
__device__ float  g_WtKV[DD*D2];
__device__ float  g_WtQ[DD*DD];
__device__ float  g_WtO[DD*DD];

// ---------------- helpers ----------------
__device__ __forceinline__ float warp_sum(float v) {
    #pragma unroll
    for (int o = 16; o > 0; o >>= 1) v += __shfl_xor_sync(0xffffffffu, v, o);
    return v;
}

__device__ __forceinline__ void h2fma(float coef, uint2 v, float4& acc) {
    __half2 h0 = *reinterpret_cast<__half2*>(&v.x);
    __half2 h1 = *reinterpret_cast<__half2*>(&v.y);
    float2 f0 = __half22float2(h0);
    float2 f1 = __half22float2(h1);
    acc.x = fmaf(coef, f0.x, acc.x);
    acc.y = fmaf(coef, f0.y, acc.y);
    acc.z = fmaf(coef, f1.x, acc.z);
    acc.w = fmaf(coef, f1.y, acc.w);
}

// ---------------- CSR construction (batched over 3 graphs) ----------------
__global__ void k_zero3() {
    int i = blockIdx.x * blockDim.x + threadIdx.x;
    if (i < 3 * NN) g_deg[i] = 0;
}

__global__ void k_count3(const int* __restrict__ e0,
                         const int* __restrict__ e1,
                         const int* __restrict__ e2) {
    int g = blockIdx.y;
    const int* ep = (g == 0) ? e0 : (g == 1) ? e1 : e2;
    int e = blockIdx.x * blockDim.x + threadIdx.x;
    if (e < EE) atomicAdd(&g_deg[g * NN + ep[e]], 1);
}

__global__ void k_scanA() {
    __shared__ int sh[256];
    int g = blockIdx.y;
    int i = blockIdx.x * 256 + threadIdx.x;
    int d = (i < NN) ? g_deg[g * NN + i] : 0;
    if (i < NN) g_dinv[g * NN + i] = (d > 0) ? rsqrtf((float)d) : 0.f;
    sh[threadIdx.x] = d;
    __syncthreads();
    #pragma unroll
    for (int o = 128; o > 0; o >>= 1) {
        if (threadIdx.x < o) sh[threadIdx.x] += sh[threadIdx.x + o];
        __syncthreads();
    }
    if (threadIdx.x == 0) g_bsum[g * SBLK + blockIdx.x] = sh[0];
}

__global__ void k_scanB() {
    __shared__ int sh[256];
    int tid = threadIdx.x;
    for (int g = 0; g < 3; g++) {
        int v = (tid < SBLK) ? g_bsum[g * SBLK + tid] : 0;
        sh[tid] = v;
        __syncthreads();
        #pragma unroll
        for (int o = 1; o < 256; o <<= 1) {
            int t = (tid >= o) ? sh[tid - o] : 0;
            __syncthreads();
            sh[tid] += t;
            __syncthreads();
        }
        if (tid < SBLK) g_bscan[g * SBLK + tid] = sh[tid] - v;
        if (tid == 255) g_offs[g * NN1 + NN] = sh[255];
        __syncthreads();
    }
}

__global__ void k_scanC() {
    __shared__ int sh[256];
    int g = blockIdx.y;
    int i = blockIdx.x * 256 + threadIdx.x;
    int tid = threadIdx.x;
    int d = (i < NN) ? g_deg[g * NN + i] : 0;
    sh[tid] = d;
    __syncthreads();
    #pragma unroll
    for (int o = 1; o < 256; o <<= 1) {
        int t = (tid >= o) ? sh[tid - o] : 0;
        __syncthreads();
        sh[tid] += t;
        __syncthreads();
    }
    if (i < NN) {
        int off = g_bscan[g * SBLK + blockIdx.x] + sh[tid] - d;
        g_offs[g * NN1 + i] = off;
        g_cur[g * NN + i]   = off;
    }
}

// fill CSR + coef for layer 1 (glr1 graph-independent)
__global__ void k_fill3(const int* __restrict__ e0,
                        const int* __restrict__ e1,
                        const int* __restrict__ e2) {
    int g = blockIdx.y;
    const int* ep = (g == 0) ? e0 : (g == 1) ? e1 : e2;
    int e = blockIdx.x * blockDim.x + threadIdx.x;
    if (e >= EE) return;
    int row = ep[e];
    int col = ep[EE + e];
    int pos = atomicAdd(&g_cur[g * NN + row], 1);
    g_erow[g * EE + pos] = row;
    float coef = tanhf(g_glr1[row].x + g_glr1[col].y)
               * g_dinv[g * NN + row] * g_dinv[g * NN + col];
    g_ecc[g * EE + pos] = make_float2(__int_as_float(col), coef);
}

// coef for layer 2
__global__ void k_coef2_3() {
    int g = blockIdx.y;
    int e = blockIdx.x * blockDim.x + threadIdx.x;
    if (e >= EE) return;
    int row = g_erow[g * EE + e];
    int col = __float_as_int(g_ecc[g * EE + e].x);
    float coef = tanhf(g_glr2[g * NN + row].x + g_glr2[g * NN + col].y)
               * g_dinv[g * NN + row] * g_dinv[g * NN + col];
    g_ecc[g * EE + e].y = coef;
}

// ---------------- x -> fp16, and glr1 ----------------
__global__ void k_x16(const float2* __restrict__ x2) {
    int i = blockIdx.x * blockDim.x + threadIdx.x;
    if (i < NN * DD / 2) {
        float2 v = x2[i];
        reinterpret_cast<__half2*>(g_X16)[i] = __floats2half2_rn(v.x, v.y);
    }
}

__global__ void k_glr1(const float* __restrict__ x,
                       const float* __restrict__ al,
                       const float* __restrict__ ar) {
    int n = (blockIdx.x * blockDim.x + threadIdx.x) >> 5;
    int lane = threadIdx.x & 31;
    if (n >= NN) return;
    int base = n * DD;
    float gl = 0.f, gr = 0.f;
    #pragma unroll
    for (int i = 0; i < 3; i++) {
        int d = lane + 32 * i;
        float y = x[base + d];
        gl += y * al[d];
        gr += y * ar[d];
    }
    gl = warp_sum(gl);
    gr = warp_sum(gr);
    if (lane == 0) g_glr1[n] = make_float2(gl, gr);
}

// ---------------- fp16 gather core ----------------
// acc = EPS*x[n] (fp32) + sum_j coef_j * src16[col_j]; lane<24 handles 4 vals.
__device__ __forceinline__ float4 gather_row16(const uint2* __restrict__ src,
                                               const float4* __restrict__ x4,
                                               const float2* __restrict__ ecc,
                                               int s, int e,
                                               int n, int lane, bool act) {
    float4 acc = make_float4(0.f, 0.f, 0.f, 0.f);
    if (act) {
        float4 xv = __ldg(&x4[n * RW + lane]);
        acc = make_float4(EPSV * xv.x, EPSV * xv.y, EPSV * xv.z, EPSV * xv.w);
    }
    int j = s;
    for (; j + 8 <= e; j += 8) {
        float2 c0 = __ldg(&ecc[j + 0]);
        float2 c1 = __ldg(&ecc[j + 1]);
        float2 c2 = __ldg(&ecc[j + 2]);
        float2 c3 = __ldg(&ecc[j + 3]);
        float2 c4 = __ldg(&ecc[j + 4]);
        float2 c5 = __ldg(&ecc[j + 5]);
        float2 c6 = __ldg(&ecc[j + 6]);
        float2 c7 = __ldg(&ecc[j + 7]);
        if (act) {
            uint2 v0 = __ldg(&src[__float_as_int(c0.x) * RW + lane]);
            uint2 v1 = __ldg(&src[__float_as_int(c1.x) * RW + lane]);
            uint2 v2 = __ldg(&src[__float_as_int(c2.x) * RW + lane]);
            uint2 v3 = __ldg(&src[__float_as_int(c3.x) * RW + lane]);
            uint2 v4 = __ldg(&src[__float_as_int(c4.x) * RW + lane]);
            uint2 v5 = __ldg(&src[__float_as_int(c5.x) * RW + lane]);
            uint2 v6 = __ldg(&src[__float_as_int(c6.x) * RW + lane]);
            uint2 v7 = __ldg(&src[__float_as_int(c7.x) * RW + lane]);
            h2fma(c0.y, v0, acc);
            h2fma(c1.y, v1, acc);
            h2fma(c2.y, v2, acc);
            h2fma(c3.y, v3, acc);
            h2fma(c4.y, v4, acc);
            h2fma(c5.y, v5, acc);
            h2fma(c6.y, v6, acc);
            h2fma(c7.y, v7, acc);
        }
    }
    for (; j < e; j++) {
        float2 c = __ldg(&ecc[j]);
        if (act) {
            uint2 v = __ldg(&src[__float_as_int(c.x) * RW + lane]);
            h2fma(c.y, v, acc);
        }
    }
    return acc;
}

// layer-1 gather: src=X16, dst=Y16[g] (relu), epilogue glr2[g] from fp32 acc
__global__ void k_gatherA3(const float4* __restrict__ x4,
                           const float4* __restrict__ al2,
                           const float4* __restrict__ ar2) {
    int g = blockIdx.y;
    int n = (blockIdx.x * blockDim.x + threadIdx.x) >> 5;
    int lane = threadIdx.x & 31;
    if (n >= NN) return;
    bool act = lane < RW;
    int s = g_offs[g * NN1 + n], e = g_offs[g * NN1 + n + 1];
    const uint2* src = reinterpret_cast<const uint2*>(g_X16);
    float4 acc = gather_row16(src, x4, g_ecc + g * EE, s, e, n, lane, act);
    float gl = 0.f, gr = 0.f;
    if (act) {
        acc.x = fmaxf(acc.x, 0.f); acc.y = fmaxf(acc.y, 0.f);
        acc.z = fmaxf(acc.z, 0.f); acc.w = fmaxf(acc.w, 0.f);
        __half2 h0 = __floats2half2_rn(acc.x, acc.y);
        __half2 h1 = __floats2half2_rn(acc.z, acc.w);
        uint2 st;
        st.x = *reinterpret_cast<uint32_t*>(&h0);
        st.y = *reinterpret_cast<uint32_t*>(&h1);
        reinterpret_cast<uint2*>(g_Y16)[(g * NN + n) * RW + lane] = st;
        float4 a = __ldg(&al2[lane]);
        float4 r = __ldg(&ar2[lane]);
        gl = acc.x * a.x + acc.y * a.y + acc.z * a.z + acc.w * a.w;
        gr = acc.x * r.x + acc.y * r.y + acc.z * r.z + acc.w * r.w;
    }
    gl = warp_sum(gl);
    gr = warp_sum(gr);
    if (lane == 0) g_glr2[g * NN + n] = make_float2(gl, gr);
}

// layer-2 gather: src=Y16[g], dst=SAB[g] fp32
__global__ void k_gatherB3(const float4* __restrict__ x4) {
    int g = blockIdx.y;
    int n = (blockIdx.x * blockDim.x + threadIdx.x) >> 5;
    int lane = threadIdx.x & 31;
    if (n >= NN) return;
    bool act = lane < RW;
    int s = g_offs[g * NN1 + n], e = g_offs[g * NN1 + n + 1];
    const uint2* src = reinterpret_cast<const uint2*>(g_Y16) + g * NN * RW;
    float4 acc = gather_row16(src, x4, g_ecc + g * EE, s, e, n, lane, act);
    if (act)
        reinterpret_cast<float4*>(g_SAB)[(g * NN + n) * RW + lane] = acc;
}

// ---------------- gating + concat ----------------
__global__ void k_combine(const float* __restrict__ x,
                          const float* __restrict__ wga,
                          const float* __restrict__ bga,
                          const float* __restrict__ wgb,
                          const float* __restrict__ bgb) {
    int n = (blockIdx.x * blockDim.x + threadIdx.x) >> 5;
    int lane = threadIdx.x & 31;
    if (n >= NN) return;
    int base = n * DD;
    float l0 = 0.f, l1 = 0.f, m0 = 0.f, m1 = 0.f;
    float sv[3], av[3], bv[3];
    #pragma unroll
    for (int i = 0; i < 3; i++) {
        int d = lane + 32 * i;
        float xx = x[base + d];
        l0 += xx * wga[d];
        l1 += xx * wga[DD + d];
        m0 += xx * wgb[d];
        m1 += xx * wgb[DD + d];
        sv[i] = fmaxf(g_SAB[0 * NN * DD + base + d], 0.f);
        av[i] = fmaxf(g_SAB[1 * NN * DD + base + d], 0.f);
        bv[i] = fmaxf(g_SAB[2 * NN * DD + base + d], 0.f);
    }
    l0 = warp_sum(l0); l1 = warp_sum(l1);
    m0 = warp_sum(m0); m1 = warp_sum(m1);
    l0 += bga[0]; l1 += bga[1];
    m0 += bgb[0]; m1 += bgb[1];
    float ga0 = 1.f / (1.f + __expf(l1 - l0));
    float ga1 = 1.f - ga0;
    float gb0 = 1.f / (1.f + __expf(m1 - m0));
    float gb1 = 1.f - gb0;
    #pragma unroll
    for (int i = 0; i < 3; i++) {
        int d = lane + 32 * i;
        g_CAT[n * D2 + d]      = ga0 * av[i] + ga1 * sv[i];
        g_CAT[n * D2 + DD + d] = gb0 * bv[i] + gb1 * sv[i];
    }
}

__global__ void k_transpose(const float* __restrict__ w_lin,
                            const float* __restrict__ w_qkv,
                            const float* __restrict__ w_o) {
    int t = blockIdx.x * blockDim.x + threadIdx.x;
    if (t >= D2 * DD) return;
    {
        int k = t / DD, j = t % DD;
        g_WtLin[t] = w_lin[j * D2 + k];
    }
    {
        int c = t / D2, r = t % D2;
        g_WtKV[t] = w_qkv[(DD + r) * DD + c];
    }
    if (t < DD * DD) {
        int c = t / DD, j = t % DD;
        g_WtQ[t] = w_qkv[j * DD + c];
        g_WtO[t] = w_o[j * DD + c];
    }
}

// h = relu(CAT @ w_lin^T + b_lin)
__global__ void k_gemm_h(const float* __restrict__ b_lin) {
    __shared__ float As[32 * D2];
    int j = threadIdx.x;
    int base = blockIdx.x * 32;
    int cnt = min(32, NN - base);
    for (int idx = j; idx < cnt * D2; idx += DD) {
        int r = idx / D2, c = idx % D2;
        As[r * D2 + c] = g_CAT[(base + r) * D2 + c];
    }
    __syncthreads();
    float acc[32];
    #pragma unroll
    for (int m = 0; m < 32; m++) acc[m] = 0.f;
    const float4* As4 = reinterpret_cast<const float4*>(As);
    #pragma unroll 4
    for (int k4 = 0; k4 < D2 / 4; k4++) {
        int k = k4 * 4;
        float w0 = g_WtLin[(k + 0) * DD + j];
        float w1 = g_WtLin[(k + 1) * DD + j];
        float w2 = g_WtLin[(k + 2) * DD + j];
        float w3 = g_WtLin[(k + 3) * DD + j];
        #pragma unroll
        for (int m = 0; m < 32; m++) {
            float4 a = As4[m * (D2 / 4) + k4];
            acc[m] += a.x * w0 + a.y * w1 + a.z * w2 + a.w * w3;
        }
    }
    float bj = b_lin[j];
    for (int m = 0; m < cnt; m++)
        g_H[(base + m) * DD + j] = fmaxf(acc[m] + bj, 0.f);
}

// K,V per node
__global__ void k_gemm_kv(const float* __restrict__ b_qkv) {
    __shared__ float As[32 * DD];
    int j = threadIdx.x;
    int base = blockIdx.x * 32;
    int cnt = min(32, NN - base);
    for (int idx = j; idx < cnt * DD; idx += D2) {
        int r = idx / DD, c = idx % DD;
        As[r * DD + c] = g_H[(base + r) * DD + c];
    }
    __syncthreads();
    float acc[32];
    #pragma unroll
    for (int m = 0; m < 32; m++) acc[m] = 0.f;
    const float4* As4 = reinterpret_cast<const float4*>(As);
    #pragma unroll 4
    for (int k4 = 0; k4 < DD / 4; k4++) {
        int k = k4 * 4;
        float w0 = g_WtKV[(k + 0) * D2 + j];
        float w1 = g_WtKV[(k + 1) * D2 + j];
        float w2 = g_WtKV[(k + 2) * D2 + j];
        float w3 = g_WtKV[(k + 3) * D2 + j];
        #pragma unroll
        for (int m = 0; m < 32; m++) {
            float4 a = As4[m * (DD / 4) + k4];
            acc[m] += a.x * w0 + a.y * w1 + a.z * w2 + a.w * w3;
        }
    }
    float bj = b_qkv[DD + j];
    if (j < DD) {
        for (int m = 0; m < cnt; m++)
            g_KN[(base + m) * DD + j] = acc[m] + bj;
    } else {
        int jj = j - DD;
        for (int m = 0; m < cnt; m++)
            g_VN[(base + m) * DD + jj] = acc[m] + bj;
    }
}

// attention: block per group (128 threads); only row l=0 needed.
__global__ void k_attn(const int* __restrict__ target_ids,
                       const int* __restrict__ target_lens,
                       const float* __restrict__ b_qkv,
                       const float* __restrict__ b_o,
                       float* __restrict__ out) {
    __shared__ int   sn[LL];
    __shared__ int   slen;
    __shared__ float hrow[DD];
    __shared__ float qs[DD];
    __shared__ float Ks[LL * 97];
    __shared__ float sc[HH * 68];
    __shared__ float cs[DD];

    int g = blockIdx.x;
    int tid = threadIdx.x;

    if (tid < LL) sn[tid] = target_ids[g * LL + tid];
    if (tid == 64) slen = target_lens[g];
    __syncthreads();

    if (tid < DD) hrow[tid] = g_H[sn[0] * DD + tid];
    __syncthreads();

    for (int idx = tid; idx < LL * DD; idx += blockDim.x) {
        int m = idx / DD, c = idx % DD;
        Ks[m * 97 + c] = g_KN[sn[m] * DD + c];
    }
    if (tid < DD) {
        float s = 0.f;
        #pragma unroll 8
        for (int c = 0; c < DD; c++) s += hrow[c] * g_WtQ[c * DD + tid];
        qs[tid] = (s + b_qkv[tid]) * QSCALE;
    }
    __syncthreads();

    int len = slen;
    if (tid < LL && tid < len) {
        int m = tid;
        const float* kr = &Ks[m * 97];
        #pragma unroll
        for (int h = 0; h < HH; h++) {
            float s = 0.f;
            #pragma unroll
            for (int d = 0; d < 12; d++) s += qs[h * 12 + d] * kr[h * 12 + d];
            sc[h * 68 + m] = s;
        }
    }
    __syncthreads();

    if (tid < HH) {
        float* row = &sc[tid * 68];
        float mx = row[0];
        for (int m = 1; m < len; m++) mx = fmaxf(mx, row[m]);
        float sum = 0.f;
        for (int m = 0; m < len; m++) {
            float e = __expf(row[m] - mx);
            row[m] = e;
            sum += e;
        }
        float inv = 1.f / sum;
        for (int m = 0; m < len; m++) row[m] *= inv;
    }
    __syncthreads();

    if (tid < LL) {
        float wv = 0.f;
        if (tid < len) {
            #pragma unroll
            for (int h = 0; h < HH; h++) wv += sc[h * 68 + tid];
            wv *= (1.f / HH);
        }
        out[GG * DD + g * LL + tid] = wv;
    }
    if (tid < DD) {
        int h = tid / 12;
        float a = 0.f;
        for (int m = 0; m < len; m++)
            a += sc[h * 68 + m] * g_VN[sn[m] * DD + tid];
        cs[tid] = a;
    }
    __syncthreads();

    if (tid < DD) {
        float o = b_o[tid];
        #pragma unroll 8
        for (int c = 0; c < DD; c++) o += cs[c] * g_WtO[c * DD + tid];
        out[g * DD + tid] = o;
    }
}

// ---------------- launch ----------------
extern "C" void kernel_launch(void* const* d_in, const int* in_sizes, int n_in,
                              void* d_out, int out_size) {
    const float* x     = (const float*)d_in[0];
    const float* a_l   = (const float*)d_in[1];
    const float* a_r   = (const float*)d_in[2];
    const float* w_ga  = (const float*)d_in[3];
    const float* b_ga  = (const float*)d_in[4];
    const float* w_gb  = (const float*)d_in[5];
    const float* b_gb  = (const float*)d_in[6];
    const float* w_lin = (const float*)d_in[7];
    const float* b_lin = (const float*)d_in[8];
    const float* w_qkv = (const float*)d_in[9];
    const float* b_qkv = (const float*)d_in[10];
    const float* w_o   = (const float*)d_in[11];
    const float* b_o   = (const float*)d_in[12];
    const int*   e0    = (const int*)d_in[13];
    const int*   e1    = (const int*)d_in[14];
    const int*   e2    = (const int*)d_in[15];
    const int*   target_ids  = (const int*)d_in[16];
    const int*   target_lens = (const int*)d_in[17];
    float* out = (float*)d_out;

    const float4* x4  = (const float4*)x;
    const float2* x2  = (const float2*)x;
    const float4* al2 = (const float4*)(a_l + DD);
    const float4* ar2 = (const float4*)(a_r + DD);

    dim3 eg(EBLK, 3), sg(SBLK, 3), ng(NODEB, 3);

    k_transpose<<<(D2 * DD + 255) / 256, 256>>>(w_lin, w_qkv, w_o);
    k_x16<<<(NN * DD / 2 + 255) / 256, 256>>>(x2);
    k_glr1<<<NODEB, 256>>>(x, a_l, a_r);

    k_zero3<<<(3 * NN + 255) / 256, 256>>>();
    k_count3<<<eg, 256>>>(e0, e1, e2);
    k_scanA<<<sg, 256>>>();
    k_scanB<<<1, 256>>>();
    k_scanC<<<sg, 256>>>();
    k_fill3<<<eg, 256>>>(e0, e1, e2);
    k_gatherA3<<<ng, 256>>>(x4, al2, ar2);
    k_coef2_3<<<eg, 256>>>();
    k_gatherB3<<<ng, 256>>>(x4);

    k_combine<<<NODEB, 256>>>(x, w_ga, b_ga, w_gb, b_gb);
    k_gemm_h<<<(NN + 31) / 32, DD>>>(b_lin);
    k_gemm_kv<<<(NN + 31) / 32, D2>>>(b_qkv);
    k_attn<<<GG, 128>>>(target_ids, target_lens, b_qkv, b_o, out);
}

// round 8
// speedup vs baseline: 1.6490x; 1.0316x over previous
#include <cuda_runtime.h>
#include <cuda_fp16.h>
#include <math.h>
#include <stdint.h>

#define NN   50000
#define NN1  50001
#define DD   96
#define EE   800000
#define GG   2048
#define LL   64
#define HH   8
#define D2   192
#define EPSV 0.3f
#define QSCALE 0.2886751345948129f  // 1/sqrt(12)
#define RW   24                      // float4 per fp32 row; 8B-chunks per fp16 row
#define SBLK 196
#define EBLK 3125
#define NODEB 6250

// ---------------- device scratch ----------------
__device__ int    g_deg[3*NN];        // zero at load; re-zeroed by k_scanCp each run
__device__ int    g_offs[3*NN1];
__device__ int    g_cur[3*NN];
__device__ int    g_bsum[3*SBLK];
__device__ __align__(16) int    g_colc[3*EE];
__device__ __align__(16) float2 g_ecc[3*EE];     // (col bits, coef)
__device__ float  g_glx1[NN];
__device__ float  g_gr1[NN];
__device__ float2 g_gd1[3*NN];                   // (gr1, dinv[g])
__device__ float  g_glx2[3*NN];
__device__ float2 g_gd2[3*NN];                   // (gr2[g], dinv[g])
__device__ __align__(16) __half g_X16[NN*DD];
__device__ __align__(16) __half g_Y16[3*NN*DD];
__device__ __align__(16) float  g_CAT[NN*D2];
__device__ __align__(16) float  g_H[NN*DD];
__device__ __align__(16) float  g_KN[NN*DD];
__device__ __align__(16) float  g_VN[NN*DD];
__device__ float  g_WtLin[D2*DD];
__device__ float  g_WtKV[DD*D2];
__device__ float  g_WtQ[DD*DD];
__device__ float  g_WtO[DD*DD];

// ---------------- helpers ----------------
__device__ __forceinline__ float warp_sum(float v) {
    #pragma unroll
    for (int o = 16; o > 0; o >>= 1) v += __shfl_xor_sync(0xffffffffu, v, o);
    return v;
}

__device__ __forceinline__ void h2fma(float coef, uint2 v, float4& acc) {
    __half2 h0 = *reinterpret_cast<__half2*>(&v.x);
    __half2 h1 = *reinterpret_cast<__half2*>(&v.y);
    float2 f0 = __half22float2(h0);
    float2 f1 = __half22float2(h1);
    acc.x = fmaf(coef, f0.x, acc.x);
    acc.y = fmaf(coef, f0.y, acc.y);
    acc.z = fmaf(coef, f1.x, acc.z);
    acc.w = fmaf(coef, f1.y, acc.w);
}

// ---------------- prep: X16 + layer-1 gl/gr ----------------
__global__ void k_prep0(const float4* __restrict__ x4,
                        const float4* __restrict__ al1,
                        const float4* __restrict__ ar1) {
    int n = (blockIdx.x * blockDim.x + threadIdx.x) >> 5;
    int lane = threadIdx.x & 31;
    if (n >= NN) return;
    float gl = 0.f, gr = 0.f;
    if (lane < RW) {
        float4 xv = __ldg(&x4[n * RW + lane]);
        __half2 h0 = __floats2half2_rn(xv.x, xv.y);
        __half2 h1 = __floats2half2_rn(xv.z, xv.w);
        uint2 st;
        st.x = *reinterpret_cast<uint32_t*>(&h0);
        st.y = *reinterpret_cast<uint32_t*>(&h1);
        reinterpret_cast<uint2*>(g_X16)[n * RW + lane] = st;
        float4 a = __ldg(&al1[lane]);
        float4 r = __ldg(&ar1[lane]);
        gl = xv.x * a.x + xv.y * a.y + xv.z * a.z + xv.w * a.w;
        gr = xv.x * r.x + xv.y * r.y + xv.z * r.z + xv.w * r.w;
    }
    gl = warp_sum(gl);
    gr = warp_sum(gr);
    if (lane == 0) { g_glx1[n] = gl; g_gr1[n] = gr; }
}

// ---------------- CSR construction ----------------
__global__ void k_count3(const int* __restrict__ e0,
                         const int* __restrict__ e1,
                         const int* __restrict__ e2) {
    int g = blockIdx.y;
    const int* ep = (g == 0) ? e0 : (g == 1) ? e1 : e2;
    int e = blockIdx.x * blockDim.x + threadIdx.x;
    if (e < EE) atomicAdd(&g_deg[g * NN + ep[e]], 1);
}

// per-block sums + dinv + pack gd1=(gr1, dinv)
__global__ void k_scanA() {
    __shared__ int sh[256];
    int g = blockIdx.y;
    int i = blockIdx.x * 256 + threadIdx.x;
    int d = (i < NN) ? g_deg[g * NN + i] : 0;
    if (i < NN) {
        float dv = (d > 0) ? rsqrtf((float)d) : 0.f;
        g_gd1[g * NN + i] = make_float2(g_gr1[i], dv);
    }
    sh[threadIdx.x] = d;
    __syncthreads();
    #pragma unroll
    for (int o = 128; o > 0; o >>= 1) {
        if (threadIdx.x < o) sh[threadIdx.x] += sh[threadIdx.x + o];
        __syncthreads();
    }
    if (threadIdx.x == 0) g_bsum[g * SBLK + blockIdx.x] = sh[0];
}

// merged scanB+scanC: each block redundantly scans bsum, then local scan,
// writes offs/cur, then zeroes deg for next run.
__global__ void k_scanCp() {
    __shared__ int shb[256];
    __shared__ int sh[256];
    int g = blockIdx.y;
    int bx = blockIdx.x;
    int tid = threadIdx.x;
    int bv = (tid < SBLK) ? g_bsum[g * SBLK + tid] : 0;
    shb[tid] = bv;
    __syncthreads();
    #pragma unroll
    for (int o = 1; o < 256; o <<= 1) {
        int t = (tid >= o) ? shb[tid - o] : 0;
        __syncthreads();
        shb[tid] += t;
        __syncthreads();
    }
    // shb now inclusive scan of bsum
    int blockPrefix = (bx > 0) ? shb[bx - 1] : 0;
    if (bx == 0 && tid == 0) g_offs[g * NN1 + NN] = shb[SBLK - 1];

    int i = bx * 256 + tid;
    int d = (i < NN) ? g_deg[g * NN + i] : 0;
    sh[tid] = d;
    __syncthreads();
    #pragma unroll
    for (int o = 1; o < 256; o <<= 1) {
        int t = (tid >= o) ? sh[tid - o] : 0;
        __syncthreads();
        sh[tid] += t;
        __syncthreads();
    }
    if (i < NN) {
        int off = blockPrefix + sh[tid] - d;
        g_offs[g * NN1 + i] = off;
        g_cur[g * NN + i]   = off;
        g_deg[g * NN + i]   = 0;     // ready for next run
    }
}

// minimal CSR fill (col only)
__global__ void k_fill3(const int* __restrict__ e0,
                        const int* __restrict__ e1,
                        const int* __restrict__ e2) {
    int g = blockIdx.y;
    const int* ep = (g == 0) ? e0 : (g == 1) ? e1 : e2;
    int e = blockIdx.x * blockDim.x + threadIdx.x;
    if (e >= EE) return;
    int row = ep[e];
    int col = ep[EE + e];
    int pos = atomicAdd(&g_cur[g * NN + row], 1);
    g_colc[g * EE + pos] = col;
}

// node-parallel coef: warp per node; one random 8B load per edge.
// glx stride: 0 for layer1 (shared), NN for layer2 (per-graph)
__global__ void k_coefN(const float* __restrict__ glx, int glx_stride,
                        const float2* __restrict__ gd) {
    int g = blockIdx.y;
    int n = (blockIdx.x * blockDim.x + threadIdx.x) >> 5;
    int lane = threadIdx.x & 31;
    if (n >= NN) return;
    const float2* gdg = gd + g * NN;
    float glrow = glx[g * glx_stride + n];
    float dvrow = gdg[n].y;
    int s = g_offs[g * NN1 + n], e = g_offs[g * NN1 + n + 1];
    for (int j = s + lane; j < e; j += 32) {
        int col = g_colc[g * EE + j];
        float2 cd = __ldg(&gdg[col]);
        float coef = tanhf(glrow + cd.x) * dvrow * cd.y;
        g_ecc[g * EE + j] = make_float2(__int_as_float(col), coef);
    }
}

// ---------------- fp16 gather core ----------------
__device__ __forceinline__ float4 gather_row16(const uint2* __restrict__ src,
                                               const float2* __restrict__ ecc,
                                               int s, int e,
                                               int lane, bool act, float4 acc) {
    int j = s;
    for (; j + 8 <= e; j += 8) {
        float2 c0 = __ldg(&ecc[j + 0]);
        float2 c1 = __ldg(&ecc[j + 1]);
        float2 c2 = __ldg(&ecc[j + 2]);
        float2 c3 = __ldg(&ecc[j + 3]);
        float2 c4 = __ldg(&ecc[j + 4]);
        float2 c5 = __ldg(&ecc[j + 5]);
        float2 c6 = __ldg(&ecc[j + 6]);
        float2 c7 = __ldg(&ecc[j + 7]);
        if (act) {
            uint2 v0 = __ldg(&src[__float_as_int(c0.x) * RW + lane]);
            uint2 v1 = __ldg(&src[__float_as_int(c1.x) * RW + lane]);
            uint2 v2 = __ldg(&src[__float_as_int(c2.x) * RW + lane]);
            uint2 v3 = __ldg(&src[__float_as_int(c3.x) * RW + lane]);
            uint2 v4 = __ldg(&src[__float_as_int(c4.x) * RW + lane]);
            uint2 v5 = __ldg(&src[__float_as_int(c5.x) * RW + lane]);
            uint2 v6 = __ldg(&src[__float_as_int(c6.x) * RW + lane]);
            uint2 v7 = __ldg(&src[__float_as_int(c7.x) * RW + lane]);
            h2fma(c0.y, v0, acc); h2fma(c1.y, v1, acc);
            h2fma(c2.y, v2, acc); h2fma(c3.y, v3, acc);
            h2fma(c4.y, v4, acc); h2fma(c5.y, v5, acc);
            h2fma(c6.y, v6, acc); h2fma(c7.y, v7, acc);
        }
    }
    for (; j < e; j++) {
        float2 c = __ldg(&ecc[j]);
        if (act) {
            uint2 v = __ldg(&src[__float_as_int(c.x) * RW + lane]);
            h2fma(c.y, v, acc);
        }
    }
    return acc;
}

// layer-1 gather: src=X16, dst=Y16[g] (relu); epilogue glx2/gd2
__global__ void k_gatherA3(const float4* __restrict__ x4,
                           const float4* __restrict__ al2,
                           const float4* __restrict__ ar2) {
    int g = blockIdx.y;
    int n = (blockIdx.x * blockDim.x + threadIdx.x) >> 5;
    int lane = threadIdx.x & 31;
    if (n >= NN) return;
    bool act = lane < RW;
    int s = g_offs[g * NN1 + n], e = g_offs[g * NN1 + n + 1];
    float4 acc = make_float4(0.f, 0.f, 0.f, 0.f);
    if (act) {
        float4 xv = __ldg(&x4[n * RW + lane]);
        acc = make_float4(EPSV * xv.x, EPSV * xv.y, EPSV * xv.z, EPSV * xv.w);
    }
    const uint2* src = reinterpret_cast<const uint2*>(g_X16);
    acc = gather_row16(src, g_ecc + g * EE, s, e, lane, act, acc);
    float gl = 0.f, gr = 0.f;
    if (act) {
        acc.x = fmaxf(acc.x, 0.f); acc.y = fmaxf(acc.y, 0.f);
        acc.z = fmaxf(acc.z, 0.f); acc.w = fmaxf(acc.w, 0.f);
        __half2 h0 = __floats2half2_rn(acc.x, acc.y);
        __half2 h1 = __floats2half2_rn(acc.z, acc.w);
        uint2 st;
        st.x = *reinterpret_cast<uint32_t*>(&h0);
        st.y = *reinterpret_cast<uint32_t*>(&h1);
        reinterpret_cast<uint2*>(g_Y16)[(g * NN + n) * RW + lane] = st;
        float4 a = __ldg(&al2[lane]);
        float4 r = __ldg(&ar2[lane]);
        gl = acc.x * a.x + acc.y * a.y + acc.z * a.z + acc.w * a.w;
        gr = acc.x * r.x + acc.y * r.y + acc.z * r.z + acc.w * r.w;
    }
    gl = warp_sum(gl);
    gr = warp_sum(gr);
    if (lane == 0) {
        g_glx2[g * NN + n] = gl;
        g_gd2[g * NN + n] = make_float2(gr, g_gd1[g * NN + n].y);
    }
}

// layer-2 gather for ALL 3 graphs + gating + CAT (fused combine)
__global__ void k_gatherBC(const float4* __restrict__ x4,
                           const float4* __restrict__ wga4,
                           const float* __restrict__ bga,
                           const float4* __restrict__ wgb4,
                           const float* __restrict__ bgb) {
    int n = (blockIdx.x * blockDim.x + threadIdx.x) >> 5;
    int lane = threadIdx.x & 31;
    if (n >= NN) return;
    bool act = lane < RW;
    float4 xv = make_float4(0.f, 0.f, 0.f, 0.f);
    if (act) xv = __ldg(&x4[n * RW + lane]);
    float4 init = make_float4(EPSV * xv.x, EPSV * xv.y, EPSV * xv.z, EPSV * xv.w);

    float4 res[3];
    #pragma unroll
    for (int g = 0; g < 3; g++) {
        int s = g_offs[g * NN1 + n], e = g_offs[g * NN1 + n + 1];
        const uint2* src = reinterpret_cast<const uint2*>(g_Y16) + g * NN * RW;
        float4 acc = gather_row16(src, g_ecc + g * EE, s, e, lane, act, init);
        acc.x = fmaxf(acc.x, 0.f); acc.y = fmaxf(acc.y, 0.f);
        acc.z = fmaxf(acc.z, 0.f); acc.w = fmaxf(acc.w, 0.f);
        res[g] = acc;
    }
    // gating: l0 = x.wga[0], l1 = x.wga[1], m0 = x.wgb[0], m1 = x.wgb[1]
    float l0 = 0.f, l1 = 0.f, m0 = 0.f, m1 = 0.f;
    if (act) {
        float4 wa0 = __ldg(&wga4[lane]);
        float4 wa1 = __ldg(&wga4[RW + lane]);
        float4 wb0 = __ldg(&wgb4[lane]);
        float4 wb1 = __ldg(&wgb4[RW + lane]);
        l0 = xv.x * wa0.x + xv.y * wa0.y + xv.z * wa0.z + xv.w * wa0.w;
        l1 = xv.x * wa1.x + xv.y * wa1.y + xv.z * wa1.z + xv.w * wa1.w;
        m0 = xv.x * wb0.x + xv.y * wb0.y + xv.z * wb0.z + xv.w * wb0.w;
        m1 = xv.x * wb1.x + xv.y * wb1.y + xv.z * wb1.z + xv.w * wb1.w;
    }
    l0 = warp_sum(l0); l1 = warp_sum(l1);
    m0 = warp_sum(m0); m1 = warp_sum(m1);
    l0 += bga[0]; l1 += bga[1];
    m0 += bgb[0]; m1 += bgb[1];
    float ga0 = 1.f / (1.f + __expf(l1 - l0));
    float ga1 = 1.f - ga0;
    float gb0 = 1.f / (1.f + __expf(m1 - m0));
    float gb1 = 1.f - gb0;
    if (act) {
        // res[0]=S (g0), res[1]=A (g1), res[2]=B (g2)
        float4 ca, cb;
        ca.x = ga0 * res[1].x + ga1 * res[0].x;
        ca.y = ga0 * res[1].y + ga1 * res[0].y;
        ca.z = ga0 * res[1].z + ga1 * res[0].z;
        ca.w = ga0 * res[1].w + ga1 * res[0].w;
        cb.x = gb0 * res[2].x + gb1 * res[0].x;
        cb.y = gb0 * res[2].y + gb1 * res[0].y;
        cb.z = gb0 * res[2].z + gb1 * res[0].z;
        cb.w = gb0 * res[2].w + gb1 * res[0].w;
        reinterpret_cast<float4*>(g_CAT)[n * (D2 / 4) + lane] = ca;
        reinterpret_cast<float4*>(g_CAT)[n * (D2 / 4) + RW + lane] = cb;
    }
}

__global__ void k_transpose(const float* __restrict__ w_lin,
                            const float* __restrict__ w_qkv,
                            const float* __restrict__ w_o) {
    int t = blockIdx.x * blockDim.x + threadIdx.x;
    if (t >= D2 * DD) return;
    {
        int k = t / DD, j = t % DD;
        g_WtLin[t] = w_lin[j * D2 + k];
    }
    {
        int c = t / D2, r = t % D2;
        g_WtKV[t] = w_qkv[(DD + r) * DD + c];
    }
    if (t < DD * DD) {
        int c = t / DD, j = t % DD;
        g_WtQ[t] = w_qkv[j * DD + c];
        g_WtO[t] = w_o[j * DD + c];
    }
}

// h = relu(CAT @ w_lin^T + b_lin)
__global__ void k_gemm_h(const float* __restrict__ b_lin) {
    __shared__ float As[32 * D2];
    int j = threadIdx.x;
    int base = blockIdx.x * 32;
    int cnt = min(32, NN - base);
    for (int idx = j; idx < cnt * D2; idx += DD) {
        int r = idx / D2, c = idx % D2;
        As[r * D2 + c] = g_CAT[(base + r) * D2 + c];
    }
    __syncthreads();
    float acc[32];
    #pragma unroll
    for (int m = 0; m < 32; m++) acc[m] = 0.f;
    const float4* As4 = reinterpret_cast<const float4*>(As);
    #pragma unroll 4
    for (int k4 = 0; k4 < D2 / 4; k4++) {
        int k = k4 * 4;
        float w0 = g_WtLin[(k + 0) * DD + j];
        float w1 = g_WtLin[(k + 1) * DD + j];
        float w2 = g_WtLin[(k + 2) * DD + j];
        float w3 = g_WtLin[(k + 3) * DD + j];
        #pragma unroll
        for (int m = 0; m < 32; m++) {
            float4 a = As4[m * (D2 / 4) + k4];
            acc[m] += a.x * w0 + a.y * w1 + a.z * w2 + a.w * w3;
        }
    }
    float bj = b_lin[j];
    for (int m = 0; m < cnt; m++)
        g_H[(base + m) * DD + j] = fmaxf(acc[m] + bj, 0.f);
}

// K,V per node
__global__ void k_gemm_kv(const float* __restrict__ b_qkv) {
    __shared__ float As[32 * DD];
    int j = threadIdx.x;
    int base = blockIdx.x * 32;
    int cnt = min(32, NN - base);
    for (int idx = j; idx < cnt * DD; idx += D2) {
        int r = idx / DD, c = idx % DD;
        As[r * DD + c] = g_H[(base + r) * DD + c];
    }
    __syncthreads();
    float acc[32];
    #pragma unroll
    for (int m = 0; m < 32; m++) acc[m] = 0.f;
    const float4* As4 = reinterpret_cast<const float4*>(As);
    #pragma unroll 4
    for (int k4 = 0; k4 < DD / 4; k4++) {
        int k = k4 * 4;
        float w0 = g_WtKV[(k + 0) * D2 + j];
        float w1 = g_WtKV[(k + 1) * D2 + j];
        float w2 = g_WtKV[(k + 2) * D2 + j];
        float w3 = g_WtKV[(k + 3) * D2 + j];
        #pragma unroll
        for (int m = 0; m < 32; m++) {
            float4 a = As4[m * (DD / 4) + k4];
            acc[m] += a.x * w0 + a.y * w1 + a.z * w2 + a.w * w3;
        }
    }
    float bj = b_qkv[DD + j];
    if (j < DD) {
        for (int m = 0; m < cnt; m++)
            g_KN[(base + m) * DD + j] = acc[m] + bj;
    } else {
        int jj = j - DD;
        for (int m = 0; m < cnt; m++)
            g_VN[(base + m) * DD + jj] = acc[m] + bj;
    }
}

// attention: block per group (128 threads); only row l=0 needed.
__global__ void k_attn(const int* __restrict__ target_ids,
                       const int* __restrict__ target_lens,
                       const float* __restrict__ b_qkv,
                       const float* __restrict__ b_o,
                       float* __restrict__ out) {
    __shared__ int   sn[LL];
    __shared__ int   slen;
    __shared__ float hrow[DD];
    __shared__ float qs[DD];
    __shared__ float Ks[LL * 97];
    __shared__ float sc[HH * 68];
    __shared__ float cs[DD];

    int g = blockIdx.x;
    int tid = threadIdx.x;

    if (tid < LL) sn[tid] = target_ids[g * LL + tid];
    if (tid == 64) slen = target_lens[g];
    __syncthreads();

    if (tid < DD) hrow[tid] = g_H[sn[0] * DD + tid];
    __syncthreads();

    for (int idx = tid; idx < LL * DD; idx += blockDim.x) {
        int m = idx / DD, c = idx % DD;
        Ks[m * 97 + c] = g_KN[sn[m] * DD + c];
    }
    if (tid < DD) {
        float s = 0.f;
        #pragma unroll 8
        for (int c = 0; c < DD; c++) s += hrow[c] * g_WtQ[c * DD + tid];
        qs[tid] = (s + b_qkv[tid]) * QSCALE;
    }
    __syncthreads();

    int len = slen;
    if (tid < LL && tid < len) {
        int m = tid;
        const float* kr = &Ks[m * 97];
        #pragma unroll
        for (int h = 0; h < HH; h++) {
            float s = 0.f;
            #pragma unroll
            for (int d = 0; d < 12; d++) s += qs[h * 12 + d] * kr[h * 12 + d];
            sc[h * 68 + m] = s;
        }
    }
    __syncthreads();

    if (tid < HH) {
        float* row = &sc[tid * 68];
        float mx = row[0];
        for (int m = 1; m < len; m++) mx = fmaxf(mx, row[m]);
        float sum = 0.f;
        for (int m = 0; m < len; m++) {
            float e = __expf(row[m] - mx);
            row[m] = e;
            sum += e;
        }
        float inv = 1.f / sum;
        for (int m = 0; m < len; m++) row[m] *= inv;
    }
    __syncthreads();

    if (tid < LL) {
        float wv = 0.f;
        if (tid < len) {
            #pragma unroll
            for (int h = 0; h < HH; h++) wv += sc[h * 68 + tid];
            wv *= (1.f / HH);
        }
        out[GG * DD + g * LL + tid] = wv;
    }
    if (tid < DD) {
        int h = tid / 12;
        float a = 0.f;
        for (int m = 0; m < len; m++)
            a += sc[h * 68 + m] * g_VN[sn[m] * DD + tid];
        cs[tid] = a;
    }
    __syncthreads();

    if (tid < DD) {
        float o = b_o[tid];
        #pragma unroll 8
        for (int c = 0; c < DD; c++) o += cs[c] * g_WtO[c * DD + tid];
        out[g * DD + tid] = o;
    }
}

// ---------------- launch ----------------
extern "C" void kernel_launch(void* const* d_in, const int* in_sizes, int n_in,
                              void* d_out, int out_size) {
    const float* x     = (const float*)d_in[0];
    const float* a_l   = (const float*)d_in[1];
    const float* a_r   = (const float*)d_in[2];
    const float* w_ga  = (const float*)d_in[3];
    const float* b_ga  = (const float*)d_in[4];
    const float* w_gb  = (const float*)d_in[5];
    const float* b_gb  = (const float*)d_in[6];
    const float* w_lin = (const float*)d_in[7];
    const float* b_lin = (const float*)d_in[8];
    const float* w_qkv = (const float*)d_in[9];
    const float* b_qkv = (const float*)d_in[10];
    const float* w_o   = (const float*)d_in[11];
    const float* b_o   = (const float*)d_in[12];
    const int*   e0    = (const int*)d_in[13];
    const int*   e1    = (const int*)d_in[14];
    const int*   e2    = (const int*)d_in[15];
    const int*   target_ids  = (const int*)d_in[16];
    const int*   target_lens = (const int*)d_in[17];
    float* out = (float*)d_out;

    const float4* x4   = (const float4*)x;
    const float4* al1  = (const float4*)a_l;
    const float4* ar1  = (const float4*)a_r;
    const float4* al2  = (const float4*)(a_l + DD);
    const float4* ar2  = (const float4*)(a_r + DD);
    const float4* wga4 = (const float4*)w_ga;
    const float4* wgb4 = (const float4*)w_gb;

    float  *pGlx1, *pGlx2;
    float2 *pGd1, *pGd2;
    cudaGetSymbolAddress((void**)&pGlx1, g_glx1);
    cudaGetSymbolAddress((void**)&pGlx2, g_glx2);
    cudaGetSymbolAddress((void**)&pGd1,  g_gd1);
    cudaGetSymbolAddress((void**)&pGd2,  g_gd2);

    dim3 eg(EBLK, 3), sg(SBLK, 3), ng(NODEB, 3);

    k_prep0<<<NODEB, 256>>>(x4, al1, ar1);
    k_count3<<<eg, 256>>>(e0, e1, e2);
    k_scanA<<<sg, 256>>>();
    k_scanCp<<<sg, 256>>>();
    k_fill3<<<eg, 256>>>(e0, e1, e2);
    k_coefN<<<ng, 256>>>(pGlx1, 0, pGd1);
    k_gatherA3<<<ng, 256>>>(x4, al2, ar2);
    k_coefN<<<ng, 256>>>(pGlx2, NN, pGd2);
    k_gatherBC<<<NODEB, 256>>>(x4, wga4, b_ga, wgb4, b_gb);

    k_transpose<<<(D2 * DD + 255) / 256, 256>>>(w_lin, w_qkv, w_o);
    k_gemm_h<<<(NN + 31) / 32, DD>>>(b_lin);
    k_gemm_kv<<<(NN + 31) / 32, D2>>>(b_qkv);
    k_attn<<<GG, 128>>>(target_ids, target_lens, b_qkv, b_o, out);
}